// round 5
// baseline (speedup 1.0000x reference)
#include <cuda_runtime.h>

#define N_NODES 8192
#define F_DIM   2048
#define E_EDGES 262144
#define H1      32
#define H2      16
#define ALPHA   0.9f

// ---------------- scratch (device globals; no allocs allowed) ----------------
__device__ float g_deg  [N_NODES];
__device__ float g_norm [N_NODES];
__device__ float g_xw   [N_NODES * H1];
__device__ float g_agg1 [N_NODES * H1];
__device__ float g_h    [N_NODES * H1];
__device__ float g_hw   [N_NODES * H2];
__device__ float g_agg2 [N_NODES * H2];
__device__ float g_zauto[N_NODES * H1];
__device__ float g_z    [N_NODES * H2];

// ---------------- small helpers ----------------
__device__ __forceinline__ float sigm(float x) {
    return __fdividef(1.0f, 1.0f + __expf(-x));
}

// ---------------- zero scratch ----------------
__global__ void zero_kernel() {
    int i = blockIdx.x * blockDim.x + threadIdx.x;
    if (i < N_NODES) g_deg[i] = 0.f;
    if (i < N_NODES * H1) { g_xw[i] = 0.f; g_agg1[i] = 0.f; g_zauto[i] = 0.f; }
    if (i < N_NODES * H2) g_agg2[i] = 0.f;
}

// ---------------- degree + norm ----------------
__global__ void deg_kernel(const int* __restrict__ dst) {
    int i = blockIdx.x * blockDim.x + threadIdx.x;
    if (i < E_EDGES) atomicAdd(&g_deg[dst[i]], 1.0f);
}

__global__ void norm_kernel() {
    int i = blockIdx.x * blockDim.x + threadIdx.x;
    if (i < N_NODES) g_norm[i] = rsqrtf(fmaxf(g_deg[i], 1.0f));
}

// ---------------- GEMM1: xw = feat @ W0  (split-K, atomic epilogue) ----------
// BM=128, BN=32(all), BK=32, SPLITK=8 -> grid (64, 8) = 512 blocks
__global__ __launch_bounds__(256) void gemm1_kernel(const float* __restrict__ feat,
                                                    const float* __restrict__ W0) {
    __shared__ float fs[32][130];  // [k][row], pad 130: even -> 8B-aligned float2 loads
    __shared__ float ws[32][36];   // [k][col], pad 36: 16B-aligned float4 loads

    const int tid = threadIdx.x;
    const int rowBase = blockIdx.x * 128;
    const int kBase = blockIdx.y * 256;  // 2048 / 8
    const int tx = tid & 7, ty = tid >> 3;
    const int r0 = ty * 4, c0 = tx * 4;

    float acc[4][4] = {};

    for (int kb = 0; kb < 256; kb += 32) {
        // load feat tile (128 rows x 32 k) transposed into fs[k][row]
        #pragma unroll
        for (int i = 0; i < 4; i++) {
            int s   = tid + i * 256;   // 0..1023 float4 slots
            int row = s >> 3;
            int kq  = s & 7;
            const float4 v = *reinterpret_cast<const float4*>(
                &feat[(size_t)(rowBase + row) * F_DIM + kBase + kb + kq * 4]);
            fs[kq * 4 + 0][row] = v.x;
            fs[kq * 4 + 1][row] = v.y;
            fs[kq * 4 + 2][row] = v.z;
            fs[kq * 4 + 3][row] = v.w;
        }
        // load W0 tile (32 k x 32 n)
        {
            int k = tid >> 3, n0 = (tid & 7) * 4;
            const float4 v = *reinterpret_cast<const float4*>(
                &W0[(size_t)(kBase + kb + k) * H1 + n0]);
            *reinterpret_cast<float4*>(&ws[k][n0]) = v;
        }
        __syncthreads();

        #pragma unroll
        for (int k = 0; k < 32; k++) {
            float2 a01 = *reinterpret_cast<const float2*>(&fs[k][r0]);
            float2 a23 = *reinterpret_cast<const float2*>(&fs[k][r0 + 2]);
            float4 b4  = *reinterpret_cast<const float4*>(&ws[k][c0]);
            float a[4] = {a01.x, a01.y, a23.x, a23.y};
            float b[4] = {b4.x, b4.y, b4.z, b4.w};
            #pragma unroll
            for (int i = 0; i < 4; i++)
                #pragma unroll
                for (int j = 0; j < 4; j++)
                    acc[i][j] += a[i] * b[j];
        }
        __syncthreads();
    }

    #pragma unroll
    for (int i = 0; i < 4; i++)
        #pragma unroll
        for (int j = 0; j < 4; j++)
            atomicAdd(&g_xw[(size_t)(rowBase + r0 + i) * H1 + c0 + j], acc[i][j]);
}

// ---------------- edge pass 1: agg1[dst] += norm[src] * xw[src] --------------
__global__ void edge_h_kernel(const int* __restrict__ src, const int* __restrict__ dst) {
    int t = blockIdx.x * blockDim.x + threadIdx.x;
    int e = t >> 5, lane = t & 31;
    if (e >= E_EDGES) return;
    int s = __ldg(&src[e]);
    int d = __ldg(&dst[e]);
    float v = g_xw[s * H1 + lane] * g_norm[s];
    atomicAdd(&g_agg1[d * H1 + lane], v);
}

// ---------------- h = relu(norm * agg1) ----------------
__global__ void relu_kernel() {
    int i = blockIdx.x * blockDim.x + threadIdx.x;
    if (i < N_NODES * H1) g_h[i] = fmaxf(g_norm[i >> 5] * g_agg1[i], 0.0f);
}

// ---------------- hw = norm * (h @ Wm) ----------------
__global__ void hw_kernel(const float* __restrict__ Wm) {
    int t = blockIdx.x * blockDim.x + threadIdx.x;
    if (t >= N_NODES * H2) return;
    int node = t >> 4, j = t & 15;
    float sum = 0.f;
    #pragma unroll
    for (int c = 0; c < H1; c++)
        sum += g_h[node * H1 + c] * __ldg(&Wm[c * H2 + j]);
    g_hw[t] = g_norm[node] * sum;
}

// ---------------- edge pass 2: gate + z_auto + agg2 (fused) ------------------
__global__ void edge2_kernel(const int* __restrict__ src, const int* __restrict__ dst,
                             const float* __restrict__ gate_w,
                             const float* __restrict__ gate_b) {
    int t = blockIdx.x * blockDim.x + threadIdx.x;
    int e = t >> 5, lane = t & 31;
    if (e >= E_EDGES) return;
    int s = __ldg(&src[e]);
    int d = __ldg(&dst[e]);
    float hs = g_h[s * H1 + lane];
    float hd = g_h[d * H1 + lane];
    // gate_in = [h_dst | h_src] . gate_w
    float gp = hd * __ldg(&gate_w[lane]) + hs * __ldg(&gate_w[H1 + lane]);
    #pragma unroll
    for (int off = 16; off > 0; off >>= 1)
        gp += __shfl_xor_sync(0xffffffffu, gp, off);
    float g  = tanhf(gp + __ldg(&gate_b[0]));
    float ew = g * g_norm[d] * g_norm[s] * ALPHA;
    atomicAdd(&g_zauto[d * H1 + lane], hs * ew);
    if (lane < H2) atomicAdd(&g_agg2[d * H2 + lane], g_hw[s * H2 + lane]);
}

// ---------------- z = noise * exp((z_auto + a*h) @ t2w) + norm*agg2 ----------
__global__ void nodez_kernel(const float* __restrict__ t2w,
                             const float* __restrict__ noise) {
    int t = blockIdx.x * blockDim.x + threadIdx.x;
    if (t >= N_NODES * H2) return;
    int node = t >> 4, j = t & 15;
    float mean = g_norm[node] * g_agg2[t];
    float sum = 0.f;
    #pragma unroll
    for (int c = 0; c < H1; c++)
        sum += (g_zauto[node * H1 + c] + ALPHA * g_h[node * H1 + c]) * __ldg(&t2w[c * H2 + j]);
    g_z[t] = noise[t] * expf(sum) + mean;
}

// ---------------- out = sigmoid(z @ z^T), 128x128 tiles, 8x8/thread ----------
__global__ __launch_bounds__(256) void zzt_kernel(float* __restrict__ out) {
    __shared__ float zr[H2][132];  // [k][row], pad 132 (mult of 4 -> float4 aligned)
    __shared__ float zc[H2][132];

    const int tid = threadIdx.x;
    const int rb = blockIdx.y * 128, cb = blockIdx.x * 128;

    // load z tiles transposed: 128 rows x 16 k each (512 float4 per tile)
    #pragma unroll
    for (int i = 0; i < 2; i++) {
        int sIdx = tid + i * 256;
        int row = sIdx >> 2, kq = sIdx & 3;
        float4 v = *reinterpret_cast<const float4*>(&g_z[(size_t)(rb + row) * H2 + kq * 4]);
        zr[kq * 4 + 0][row] = v.x; zr[kq * 4 + 1][row] = v.y;
        zr[kq * 4 + 2][row] = v.z; zr[kq * 4 + 3][row] = v.w;
        float4 w = *reinterpret_cast<const float4*>(&g_z[(size_t)(cb + row) * H2 + kq * 4]);
        zc[kq * 4 + 0][row] = w.x; zc[kq * 4 + 1][row] = w.y;
        zc[kq * 4 + 2][row] = w.z; zc[kq * 4 + 3][row] = w.w;
    }
    __syncthreads();

    const int tc = tid & 15, tr = tid >> 4;
    const int r4 = tr * 4, c4 = tc * 4;

    float acc[8][8] = {};
    #pragma unroll
    for (int k = 0; k < H2; k++) {
        float4 a0 = *reinterpret_cast<const float4*>(&zr[k][r4]);
        float4 a1 = *reinterpret_cast<const float4*>(&zr[k][r4 + 64]);
        float4 b0 = *reinterpret_cast<const float4*>(&zc[k][c4]);
        float4 b1 = *reinterpret_cast<const float4*>(&zc[k][c4 + 64]);
        float a[8] = {a0.x, a0.y, a0.z, a0.w, a1.x, a1.y, a1.z, a1.w};
        float b[8] = {b0.x, b0.y, b0.z, b0.w, b1.x, b1.y, b1.z, b1.w};
        #pragma unroll
        for (int i = 0; i < 8; i++)
            #pragma unroll
            for (int j = 0; j < 8; j++)
                acc[i][j] += a[i] * b[j];
    }

    #pragma unroll
    for (int i = 0; i < 8; i++) {
        int row = rb + r4 + (i < 4 ? i : 60 + i);  // i>=4 -> +64 + (i-4)
        float4 o0, o1;
        o0.x = sigm(acc[i][0]); o0.y = sigm(acc[i][1]);
        o0.z = sigm(acc[i][2]); o0.w = sigm(acc[i][3]);
        o1.x = sigm(acc[i][4]); o1.y = sigm(acc[i][5]);
        o1.z = sigm(acc[i][6]); o1.w = sigm(acc[i][7]);
        *reinterpret_cast<float4*>(&out[(size_t)row * N_NODES + cb + c4]) = o0;
        *reinterpret_cast<float4*>(&out[(size_t)row * N_NODES + cb + c4 + 64]) = o1;
    }
}

// ---------------- launcher ----------------
extern "C" void kernel_launch(void* const* d_in, const int* in_sizes, int n_in,
                              void* d_out, int out_size) {
    const float* feat   = (const float*)d_in[0];
    const float* W0     = (const float*)d_in[1];
    const float* Wm     = (const float*)d_in[2];
    const float* gate_w = (const float*)d_in[3];
    const float* gate_b = (const float*)d_in[4];
    const float* t2w    = (const float*)d_in[5];
    const float* noise  = (const float*)d_in[6];
    const int*   src    = (const int*)d_in[7];
    const int*   dst    = (const int*)d_in[8];
    float* out = (float*)d_out;

    zero_kernel<<<(N_NODES * H1) / 256, 256>>>();
    deg_kernel<<<E_EDGES / 256, 256>>>(dst);
    norm_kernel<<<N_NODES / 256, 256>>>();
    gemm1_kernel<<<dim3(N_NODES / 128, 8), 256>>>(feat, W0);
    edge_h_kernel<<<(E_EDGES * 32) / 256, 256>>>(src, dst);
    relu_kernel<<<(N_NODES * H1) / 256, 256>>>();
    hw_kernel<<<(N_NODES * H2) / 256, 256>>>(Wm);
    edge2_kernel<<<(E_EDGES * 32) / 256, 256>>>(src, dst, gate_w, gate_b);
    nodez_kernel<<<(N_NODES * H2) / 256, 256>>>(t2w, noise);
    zzt_kernel<<<dim3(64, 64), 256>>>(out);
}

// round 6
// speedup vs baseline: 1.2660x; 1.2660x over previous
#include <cuda_runtime.h>

#define N_NODES 8192
#define F_DIM   2048
#define E_EDGES 262144
#define H1      32
#define H2      16
#define ALPHA   0.9f

typedef unsigned long long ull;

// ---------------- scratch (device globals; no allocs allowed) ----------------
__device__ float g_deg  [N_NODES];
__device__ float g_norm [N_NODES];
__device__ float g_xw   [N_NODES * H1];
__device__ float g_agg1 [N_NODES * H1];
__device__ float g_h    [N_NODES * H1];
__device__ float g_hw   [N_NODES * H2];
__device__ float g_agg2 [N_NODES * H2];
__device__ float g_zauto[N_NODES * H1];
__device__ float g_z    [N_NODES * H2];

// ---------------- f32x2 helpers (ptxas never emits FFMA2 from C++) -----------
__device__ __forceinline__ ull dup2(float x) {
    ull r; asm("mov.b64 %0, {%1, %1};" : "=l"(r) : "f"(x)); return r;
}
__device__ __forceinline__ void ffma2(ull& d, ull a, ull b) {
    asm("fma.rn.f32x2 %0, %1, %2, %0;" : "+l"(d) : "l"(a), "l"(b));
}
__device__ __forceinline__ float2 unpk(ull v) {
    float2 r; asm("mov.b64 {%0, %1}, %2;" : "=f"(r.x), "=f"(r.y) : "l"(v)); return r;
}
__device__ __forceinline__ void red4(float* p, float a, float b, float c, float d) {
    asm volatile("red.global.add.v4.f32 [%0], {%1,%2,%3,%4};"
                 :: "l"(p), "f"(a), "f"(b), "f"(c), "f"(d) : "memory");
}
__device__ __forceinline__ float sigm(float x) {
    return __fdividef(1.0f, 1.0f + __expf(-x));
}

// ---------------- zero scratch ----------------
__global__ void zero_kernel() {
    int i = blockIdx.x * blockDim.x + threadIdx.x;
    if (i < N_NODES) g_deg[i] = 0.f;
    if (i < N_NODES * H1) { g_xw[i] = 0.f; g_agg1[i] = 0.f; g_zauto[i] = 0.f; }
    if (i < N_NODES * H2) g_agg2[i] = 0.f;
}

// ---------------- degree + norm ----------------
__global__ void deg_kernel(const int* __restrict__ dst) {
    int i = blockIdx.x * blockDim.x + threadIdx.x;
    if (i < E_EDGES) atomicAdd(&g_deg[dst[i]], 1.0f);
}

__global__ void norm_kernel() {
    int i = blockIdx.x * blockDim.x + threadIdx.x;
    if (i < N_NODES) g_norm[i] = rsqrtf(fmaxf(g_deg[i], 1.0f));
}

// ---------------- GEMM1: xw = feat @ W0 -------------------------------------
// BM=128, N=32(all), BK=32, SPLITK=16 (K-slice 128, 4 tiles) -> grid (64,16)
// A tile stored in smem as duplicated f32x2 pairs {v,v}; B pairs read natively.
// Register double-buffer: prefetch tile t+1 during compute of tile t.
__global__ __launch_bounds__(256) void gemm1_kernel(const float* __restrict__ feat,
                                                    const float* __restrict__ W0) {
    __shared__ ull   fs[128][34];   // [row][k] dup pairs; pad 34 (16B-aligned rows)
    __shared__ float ws[32][36];    // [k][col]; pad 36 (16B-aligned rows)

    const int tid = threadIdx.x;
    const int rowBase = blockIdx.x * 128;
    const int kBase   = blockIdx.y * 128;
    const int tx = tid & 7, ty = tid >> 3;
    const int r0 = ty * 4, c0 = tx * 4;

    const float* fb = feat + (size_t)rowBase * F_DIM + kBase;
    const float* wb = W0 + (size_t)kBase * H1;

    int row_[4], kq_[4];
    #pragma unroll
    for (int i = 0; i < 4; i++) { int s = i * 256 + tid; row_[i] = s >> 3; kq_[i] = s & 7; }
    const int wk = tid >> 3, wn = (tid & 7) * 4;

    ull acc0[4] = {}, acc1[4] = {};   // [row] x {j pair 0, j pair 1} -> 4x4 floats

    // prefetch tile 0
    float4 pf[4], pw;
    #pragma unroll
    for (int i = 0; i < 4; i++)
        pf[i] = *(const float4*)&fb[(size_t)row_[i] * F_DIM + kq_[i] * 4];
    pw = *(const float4*)&wb[(size_t)wk * H1 + wn];

    #pragma unroll
    for (int t = 0; t < 4; t++) {
        // commit prefetched tile to smem (A duplicated as {v,v} pairs)
        #pragma unroll
        for (int i = 0; i < 4; i++) {
            ulonglong2 lo, hi;
            lo.x = dup2(pf[i].x); lo.y = dup2(pf[i].y);
            hi.x = dup2(pf[i].z); hi.y = dup2(pf[i].w);
            *(ulonglong2*)&fs[row_[i]][kq_[i] * 4]     = lo;
            *(ulonglong2*)&fs[row_[i]][kq_[i] * 4 + 2] = hi;
        }
        *(float4*)&ws[wk][wn] = pw;
        __syncthreads();

        // prefetch next tile while computing this one
        if (t < 3) {
            #pragma unroll
            for (int i = 0; i < 4; i++)
                pf[i] = *(const float4*)&fb[(size_t)row_[i] * F_DIM + (t + 1) * 32 + kq_[i] * 4];
            pw = *(const float4*)&wb[(size_t)((t + 1) * 32 + wk) * H1 + wn];
        }

        #pragma unroll
        for (int k = 0; k < 32; k += 2) {
            ulonglong2 A0 = *(ulonglong2*)&fs[r0    ][k];
            ulonglong2 A1 = *(ulonglong2*)&fs[r0 + 1][k];
            ulonglong2 A2 = *(ulonglong2*)&fs[r0 + 2][k];
            ulonglong2 A3 = *(ulonglong2*)&fs[r0 + 3][k];
            ulonglong2 b0 = *(ulonglong2*)&ws[k    ][c0];
            ulonglong2 b1 = *(ulonglong2*)&ws[k + 1][c0];
            ffma2(acc0[0], A0.x, b0.x); ffma2(acc1[0], A0.x, b0.y);
            ffma2(acc0[1], A1.x, b0.x); ffma2(acc1[1], A1.x, b0.y);
            ffma2(acc0[2], A2.x, b0.x); ffma2(acc1[2], A2.x, b0.y);
            ffma2(acc0[3], A3.x, b0.x); ffma2(acc1[3], A3.x, b0.y);
            ffma2(acc0[0], A0.y, b1.x); ffma2(acc1[0], A0.y, b1.y);
            ffma2(acc0[1], A1.y, b1.x); ffma2(acc1[1], A1.y, b1.y);
            ffma2(acc0[2], A2.y, b1.x); ffma2(acc1[2], A2.y, b1.y);
            ffma2(acc0[3], A3.y, b1.x); ffma2(acc1[3], A3.y, b1.y);
        }
        __syncthreads();
    }

    #pragma unroll
    for (int i = 0; i < 4; i++) {
        float2 u0 = unpk(acc0[i]);
        float2 u1 = unpk(acc1[i]);
        red4(&g_xw[(size_t)(rowBase + r0 + i) * H1 + c0], u0.x, u0.y, u1.x, u1.y);
    }
}

// ---------------- edge pass 1: agg1[dst] += norm[src] * xw[src] --------------
// 8 lanes per edge, float4 + red.v4
__global__ void edge_h_kernel(const int* __restrict__ src, const int* __restrict__ dst) {
    int t = blockIdx.x * blockDim.x + threadIdx.x;
    int e = t >> 3, q = t & 7;
    if (e >= E_EDGES) return;
    int s = __ldg(&src[e]);
    int d = __ldg(&dst[e]);
    float ns = g_norm[s];
    float4 v = *(const float4*)&g_xw[s * H1 + q * 4];
    red4(&g_agg1[d * H1 + q * 4], v.x * ns, v.y * ns, v.z * ns, v.w * ns);
}

// ---------------- h = relu(norm * agg1) ----------------
__global__ void relu_kernel() {
    int i = blockIdx.x * blockDim.x + threadIdx.x;
    if (i < N_NODES * H1) g_h[i] = fmaxf(g_norm[i >> 5] * g_agg1[i], 0.0f);
}

// ---------------- hw = norm * (h @ Wm) ----------------
__global__ void hw_kernel(const float* __restrict__ Wm) {
    int t = blockIdx.x * blockDim.x + threadIdx.x;
    if (t >= N_NODES * H2) return;
    int node = t >> 4, j = t & 15;
    float sum = 0.f;
    #pragma unroll
    for (int c = 0; c < H1; c++)
        sum += g_h[node * H1 + c] * __ldg(&Wm[c * H2 + j]);
    g_hw[t] = g_norm[node] * sum;
}

// ---------------- edge pass 2: gate + z_auto + agg2 (fused, 8 lanes/edge) ----
__global__ void edge2_kernel(const int* __restrict__ src, const int* __restrict__ dst,
                             const float* __restrict__ gate_w,
                             const float* __restrict__ gate_b) {
    int t = blockIdx.x * blockDim.x + threadIdx.x;
    int e = t >> 3, q = t & 7;
    if (e >= E_EDGES) return;
    int s = __ldg(&src[e]);
    int d = __ldg(&dst[e]);
    float4 hs = *(const float4*)&g_h[s * H1 + q * 4];
    float4 hd = *(const float4*)&g_h[d * H1 + q * 4];
    float4 w0 = __ldg((const float4*)&gate_w[q * 4]);
    float4 w1 = __ldg((const float4*)&gate_w[H1 + q * 4]);
    float gp = hd.x * w0.x + hd.y * w0.y + hd.z * w0.z + hd.w * w0.w
             + hs.x * w1.x + hs.y * w1.y + hs.z * w1.z + hs.w * w1.w;
    // reduce across the 8 lanes of this edge (groups are warp-contiguous)
    gp += __shfl_xor_sync(0xffffffffu, gp, 1);
    gp += __shfl_xor_sync(0xffffffffu, gp, 2);
    gp += __shfl_xor_sync(0xffffffffu, gp, 4);
    float g  = tanhf(gp + __ldg(&gate_b[0]));
    float ew = g * g_norm[d] * g_norm[s] * ALPHA;
    red4(&g_zauto[d * H1 + q * 4], hs.x * ew, hs.y * ew, hs.z * ew, hs.w * ew);
    if (q < 4) {
        float4 hw = *(const float4*)&g_hw[s * H2 + q * 4];
        red4(&g_agg2[d * H2 + q * 4], hw.x, hw.y, hw.z, hw.w);
    }
}

// ---------------- z = noise * exp((z_auto + a*h) @ t2w) + norm*agg2 ----------
__global__ void nodez_kernel(const float* __restrict__ t2w,
                             const float* __restrict__ noise) {
    int t = blockIdx.x * blockDim.x + threadIdx.x;
    if (t >= N_NODES * H2) return;
    int node = t >> 4, j = t & 15;
    float mean = g_norm[node] * g_agg2[t];
    float sum = 0.f;
    #pragma unroll
    for (int c = 0; c < H1; c++)
        sum += (g_zauto[node * H1 + c] + ALPHA * g_h[node * H1 + c]) * __ldg(&t2w[c * H2 + j]);
    g_z[t] = noise[t] * expf(sum) + mean;
}

// ---------------- out = sigmoid(z @ z^T), 128x128 tiles, 8x8/thread, f32x2 ---
__global__ __launch_bounds__(256) void zzt_kernel(float* __restrict__ out) {
    __shared__ ull   zr[H2][130];   // [k][row] duplicated {v,v} pairs
    __shared__ float zc[H2][132];   // [k][col]

    const int tid = threadIdx.x;
    const int rb = blockIdx.y * 128, cb = blockIdx.x * 128;

    #pragma unroll
    for (int i = 0; i < 2; i++) {
        int sIdx = tid + i * 256;
        int row = sIdx >> 2, kq = sIdx & 3;
        float4 v = *(const float4*)&g_z[(size_t)(rb + row) * H2 + kq * 4];
        zr[kq * 4 + 0][row] = dup2(v.x); zr[kq * 4 + 1][row] = dup2(v.y);
        zr[kq * 4 + 2][row] = dup2(v.z); zr[kq * 4 + 3][row] = dup2(v.w);
        float4 w = *(const float4*)&g_z[(size_t)(cb + row) * H2 + kq * 4];
        zc[kq * 4 + 0][row] = w.x; zc[kq * 4 + 1][row] = w.y;
        zc[kq * 4 + 2][row] = w.z; zc[kq * 4 + 3][row] = w.w;
    }
    __syncthreads();

    const int tc = tid & 15, tr = tid >> 4;
    const int r4 = tr * 4, c4 = tc * 4;

    ull acc[8][4] = {};   // [row i][j-pair]: pairs (c4+0,1) (c4+2,3) (c4+64,65) (c4+66,67)
    #pragma unroll
    for (int k = 0; k < H2; k++) {
        ulonglong2 a01 = *(ulonglong2*)&zr[k][r4];
        ulonglong2 a23 = *(ulonglong2*)&zr[k][r4 + 2];
        ulonglong2 a45 = *(ulonglong2*)&zr[k][r4 + 64];
        ulonglong2 a67 = *(ulonglong2*)&zr[k][r4 + 66];
        ulonglong2 b01 = *(ulonglong2*)&zc[k][c4];
        ulonglong2 b23 = *(ulonglong2*)&zc[k][c4 + 64];
        ull a[8] = {a01.x, a01.y, a23.x, a23.y, a45.x, a45.y, a67.x, a67.y};
        ull b[4] = {b01.x, b01.y, b23.x, b23.y};
        #pragma unroll
        for (int i = 0; i < 8; i++) {
            ffma2(acc[i][0], a[i], b[0]);
            ffma2(acc[i][1], a[i], b[1]);
            ffma2(acc[i][2], a[i], b[2]);
            ffma2(acc[i][3], a[i], b[3]);
        }
    }

    #pragma unroll
    for (int i = 0; i < 8; i++) {
        int row = rb + r4 + (i < 4 ? i : 60 + i);
        float2 p0 = unpk(acc[i][0]), p1 = unpk(acc[i][1]);
        float2 p2 = unpk(acc[i][2]), p3 = unpk(acc[i][3]);
        float4 o0, o1;
        o0.x = sigm(p0.x); o0.y = sigm(p0.y); o0.z = sigm(p1.x); o0.w = sigm(p1.y);
        o1.x = sigm(p2.x); o1.y = sigm(p2.y); o1.z = sigm(p3.x); o1.w = sigm(p3.y);
        *reinterpret_cast<float4*>(&out[(size_t)row * N_NODES + cb + c4])      = o0;
        *reinterpret_cast<float4*>(&out[(size_t)row * N_NODES + cb + c4 + 64]) = o1;
    }
}

// ---------------- launcher ----------------
extern "C" void kernel_launch(void* const* d_in, const int* in_sizes, int n_in,
                              void* d_out, int out_size) {
    const float* feat   = (const float*)d_in[0];
    const float* W0     = (const float*)d_in[1];
    const float* Wm     = (const float*)d_in[2];
    const float* gate_w = (const float*)d_in[3];
    const float* gate_b = (const float*)d_in[4];
    const float* t2w    = (const float*)d_in[5];
    const float* noise  = (const float*)d_in[6];
    const int*   src    = (const int*)d_in[7];
    const int*   dst    = (const int*)d_in[8];
    float* out = (float*)d_out;

    zero_kernel<<<(N_NODES * H1) / 256, 256>>>();
    deg_kernel<<<E_EDGES / 256, 256>>>(dst);
    norm_kernel<<<N_NODES / 256, 256>>>();
    gemm1_kernel<<<dim3(N_NODES / 128, 16), 256>>>(feat, W0);
    edge_h_kernel<<<(E_EDGES * 8) / 256, 256>>>(src, dst);
    relu_kernel<<<(N_NODES * H1) / 256, 256>>>();
    hw_kernel<<<(N_NODES * H2) / 256, 256>>>(Wm);
    edge2_kernel<<<(E_EDGES * 8) / 256, 256>>>(src, dst, gate_w, gate_b);
    nodez_kernel<<<(N_NODES * H2) / 256, 256>>>(t2w, noise);
    zzt_kernel<<<dim3(64, 64), 256>>>(out);
}

// round 7
// speedup vs baseline: 1.2826x; 1.0131x over previous
#include <cuda_runtime.h>

#define N_NODES 8192
#define F_DIM   2048
#define E_EDGES 262144
#define H1      32
#define H2      16
#define ALPHA   0.9f

typedef unsigned long long ull;

// ---------------- scratch (device globals; no allocs allowed) ----------------
__device__ float g_deg  [N_NODES];
__device__ float g_norm [N_NODES];
__device__ float g_xw   [N_NODES * H1];
__device__ float g_agg1 [N_NODES * H1];
__device__ float g_h    [N_NODES * H1];
__device__ float g_hw   [N_NODES * H2];
__device__ float g_agg2 [N_NODES * H2];
__device__ float g_zauto[N_NODES * H1];
__device__ float g_z    [N_NODES * H2];

// ---------------- f32x2 helpers (ptxas never emits FFMA2 from C++) -----------
__device__ __forceinline__ ull dup2(float x) {
    ull r; asm("mov.b64 %0, {%1, %1};" : "=l"(r) : "f"(x)); return r;
}
__device__ __forceinline__ void ffma2(ull& d, ull a, ull b) {
    asm("fma.rn.f32x2 %0, %1, %2, %0;" : "+l"(d) : "l"(a), "l"(b));
}
__device__ __forceinline__ float2 unpk(ull v) {
    float2 r; asm("mov.b64 {%0, %1}, %2;" : "=f"(r.x), "=f"(r.y) : "l"(v)); return r;
}
__device__ __forceinline__ void red4(float* p, float a, float b, float c, float d) {
    asm volatile("red.global.add.v4.f32 [%0], {%1,%2,%3,%4};"
                 :: "l"(p), "f"(a), "f"(b), "f"(c), "f"(d) : "memory");
}
__device__ __forceinline__ float sigm(float x) {
    return __fdividef(1.0f, 1.0f + __expf(-x));
}

// ---------------- zero scratch ----------------
__global__ void zero_kernel() {
    int i = blockIdx.x * blockDim.x + threadIdx.x;
    if (i < N_NODES) g_deg[i] = 0.f;
    if (i < N_NODES * H1) { g_xw[i] = 0.f; g_agg1[i] = 0.f; g_zauto[i] = 0.f; }
    if (i < N_NODES * H2) g_agg2[i] = 0.f;
}

// ---------------- degree + norm ----------------
__global__ void deg_kernel(const int* __restrict__ dst) {
    int i = blockIdx.x * blockDim.x + threadIdx.x;
    if (i < E_EDGES) atomicAdd(&g_deg[dst[i]], 1.0f);
}

__global__ void norm_kernel() {
    int i = blockIdx.x * blockDim.x + threadIdx.x;
    if (i < N_NODES) g_norm[i] = rsqrtf(fmaxf(g_deg[i], 1.0f));
}

// ---------------- GEMM1: xw = feat @ W0 -------------------------------------
// BM=128, N=32(all), BK=32, SPLITK=16 (K-slice 128, 4 tiles) -> grid (64,16)
// A tile stored in smem as duplicated f32x2 pairs {v,v}; B pairs read natively.
// Register double-buffer: prefetch tile t+1 during compute of tile t.
__global__ __launch_bounds__(256) void gemm1_kernel(const float* __restrict__ feat,
                                                    const float* __restrict__ W0) {
    __shared__ ull   fs[128][34];   // [row][k] dup pairs; pad 34 (16B-aligned rows)
    __shared__ float ws[32][36];    // [k][col]; pad 36 (16B-aligned rows)

    const int tid = threadIdx.x;
    const int rowBase = blockIdx.x * 128;
    const int kBase   = blockIdx.y * 128;
    const int tx = tid & 7, ty = tid >> 3;
    const int r0 = ty * 4, c0 = tx * 4;

    const float* fb = feat + (size_t)rowBase * F_DIM + kBase;
    const float* wb = W0 + (size_t)kBase * H1;

    int row_[4], kq_[4];
    #pragma unroll
    for (int i = 0; i < 4; i++) { int s = i * 256 + tid; row_[i] = s >> 3; kq_[i] = s & 7; }
    const int wk = tid >> 3, wn = (tid & 7) * 4;

    ull acc0[4] = {}, acc1[4] = {};   // [row] x {j pair 0, j pair 1} -> 4x4 floats

    // prefetch tile 0
    float4 pf[4], pw;
    #pragma unroll
    for (int i = 0; i < 4; i++)
        pf[i] = *(const float4*)&fb[(size_t)row_[i] * F_DIM + kq_[i] * 4];
    pw = *(const float4*)&wb[(size_t)wk * H1 + wn];

    #pragma unroll
    for (int t = 0; t < 4; t++) {
        // commit prefetched tile to smem (A duplicated as {v,v} pairs)
        #pragma unroll
        for (int i = 0; i < 4; i++) {
            ulonglong2 lo, hi;
            lo.x = dup2(pf[i].x); lo.y = dup2(pf[i].y);
            hi.x = dup2(pf[i].z); hi.y = dup2(pf[i].w);
            *(ulonglong2*)&fs[row_[i]][kq_[i] * 4]     = lo;
            *(ulonglong2*)&fs[row_[i]][kq_[i] * 4 + 2] = hi;
        }
        *(float4*)&ws[wk][wn] = pw;
        __syncthreads();

        // prefetch next tile while computing this one
        if (t < 3) {
            #pragma unroll
            for (int i = 0; i < 4; i++)
                pf[i] = *(const float4*)&fb[(size_t)row_[i] * F_DIM + (t + 1) * 32 + kq_[i] * 4];
            pw = *(const float4*)&wb[(size_t)((t + 1) * 32 + wk) * H1 + wn];
        }

        #pragma unroll
        for (int k = 0; k < 32; k += 2) {
            ulonglong2 A0 = *(ulonglong2*)&fs[r0    ][k];
            ulonglong2 A1 = *(ulonglong2*)&fs[r0 + 1][k];
            ulonglong2 A2 = *(ulonglong2*)&fs[r0 + 2][k];
            ulonglong2 A3 = *(ulonglong2*)&fs[r0 + 3][k];
            ulonglong2 b0 = *(ulonglong2*)&ws[k    ][c0];
            ulonglong2 b1 = *(ulonglong2*)&ws[k + 1][c0];
            ffma2(acc0[0], A0.x, b0.x); ffma2(acc1[0], A0.x, b0.y);
            ffma2(acc0[1], A1.x, b0.x); ffma2(acc1[1], A1.x, b0.y);
            ffma2(acc0[2], A2.x, b0.x); ffma2(acc1[2], A2.x, b0.y);
            ffma2(acc0[3], A3.x, b0.x); ffma2(acc1[3], A3.x, b0.y);
            ffma2(acc0[0], A0.y, b1.x); ffma2(acc1[0], A0.y, b1.y);
            ffma2(acc0[1], A1.y, b1.x); ffma2(acc1[1], A1.y, b1.y);
            ffma2(acc0[2], A2.y, b1.x); ffma2(acc1[2], A2.y, b1.y);
            ffma2(acc0[3], A3.y, b1.x); ffma2(acc1[3], A3.y, b1.y);
        }
        __syncthreads();
    }

    #pragma unroll
    for (int i = 0; i < 4; i++) {
        float2 u0 = unpk(acc0[i]);
        float2 u1 = unpk(acc1[i]);
        red4(&g_xw[(size_t)(rowBase + r0 + i) * H1 + c0], u0.x, u0.y, u1.x, u1.y);
    }
}

// ---------------- edge pass 1: agg1[dst] += norm[src] * xw[src] --------------
// 8 lanes per edge, float4 + red.v4
__global__ void edge_h_kernel(const int* __restrict__ src, const int* __restrict__ dst) {
    int t = blockIdx.x * blockDim.x + threadIdx.x;
    int e = t >> 3, q = t & 7;
    if (e >= E_EDGES) return;
    int s = __ldg(&src[e]);
    int d = __ldg(&dst[e]);
    float ns = g_norm[s];
    float4 v = *(const float4*)&g_xw[s * H1 + q * 4];
    red4(&g_agg1[d * H1 + q * 4], v.x * ns, v.y * ns, v.z * ns, v.w * ns);
}

// ---------------- h = relu(norm * agg1) ----------------
__global__ void relu_kernel() {
    int i = blockIdx.x * blockDim.x + threadIdx.x;
    if (i < N_NODES * H1) g_h[i] = fmaxf(g_norm[i >> 5] * g_agg1[i], 0.0f);
}

// ---------------- hw = norm * (h @ Wm) ----------------
__global__ void hw_kernel(const float* __restrict__ Wm) {
    int t = blockIdx.x * blockDim.x + threadIdx.x;
    if (t >= N_NODES * H2) return;
    int node = t >> 4, j = t & 15;
    float sum = 0.f;
    #pragma unroll
    for (int c = 0; c < H1; c++)
        sum += g_h[node * H1 + c] * __ldg(&Wm[c * H2 + j]);
    g_hw[t] = g_norm[node] * sum;
}

// ---------------- edge pass 2: gate + z_auto + agg2 (fused, 8 lanes/edge) ----
__global__ void edge2_kernel(const int* __restrict__ src, const int* __restrict__ dst,
                             const float* __restrict__ gate_w,
                             const float* __restrict__ gate_b) {
    int t = blockIdx.x * blockDim.x + threadIdx.x;
    int e = t >> 3, q = t & 7;
    if (e >= E_EDGES) return;
    int s = __ldg(&src[e]);
    int d = __ldg(&dst[e]);
    float4 hs = *(const float4*)&g_h[s * H1 + q * 4];
    float4 hd = *(const float4*)&g_h[d * H1 + q * 4];
    float4 w0 = __ldg((const float4*)&gate_w[q * 4]);
    float4 w1 = __ldg((const float4*)&gate_w[H1 + q * 4]);
    float gp = hd.x * w0.x + hd.y * w0.y + hd.z * w0.z + hd.w * w0.w
             + hs.x * w1.x + hs.y * w1.y + hs.z * w1.z + hs.w * w1.w;
    // reduce across the 8 lanes of this edge (groups are warp-contiguous)
    gp += __shfl_xor_sync(0xffffffffu, gp, 1);
    gp += __shfl_xor_sync(0xffffffffu, gp, 2);
    gp += __shfl_xor_sync(0xffffffffu, gp, 4);
    float g  = tanhf(gp + __ldg(&gate_b[0]));
    float ew = g * g_norm[d] * g_norm[s] * ALPHA;
    red4(&g_zauto[d * H1 + q * 4], hs.x * ew, hs.y * ew, hs.z * ew, hs.w * ew);
    if (q < 4) {
        float4 hw = *(const float4*)&g_hw[s * H2 + q * 4];
        red4(&g_agg2[d * H2 + q * 4], hw.x, hw.y, hw.z, hw.w);
    }
}

// ---------------- z = noise * exp((z_auto + a*h) @ t2w) + norm*agg2 ----------
__global__ void nodez_kernel(const float* __restrict__ t2w,
                             const float* __restrict__ noise) {
    int t = blockIdx.x * blockDim.x + threadIdx.x;
    if (t >= N_NODES * H2) return;
    int node = t >> 4, j = t & 15;
    float mean = g_norm[node] * g_agg2[t];
    float sum = 0.f;
    #pragma unroll
    for (int c = 0; c < H1; c++)
        sum += (g_zauto[node * H1 + c] + ALPHA * g_h[node * H1 + c]) * __ldg(&t2w[c * H2 + j]);
    g_z[t] = noise[t] * expf(sum) + mean;
}

// ---------------- out = sigmoid(z @ z^T), 128x128 tiles, 8x8/thread, f32x2 ---
__global__ __launch_bounds__(256) void zzt_kernel(float* __restrict__ out) {
    __shared__ ull   zr[H2][130];   // [k][row] duplicated {v,v} pairs
    __shared__ float zc[H2][132];   // [k][col]

    const int tid = threadIdx.x;
    const int rb = blockIdx.y * 128, cb = blockIdx.x * 128;

    #pragma unroll
    for (int i = 0; i < 2; i++) {
        int sIdx = tid + i * 256;
        int row = sIdx >> 2, kq = sIdx & 3;
        float4 v = *(const float4*)&g_z[(size_t)(rb + row) * H2 + kq * 4];
        zr[kq * 4 + 0][row] = dup2(v.x); zr[kq * 4 + 1][row] = dup2(v.y);
        zr[kq * 4 + 2][row] = dup2(v.z); zr[kq * 4 + 3][row] = dup2(v.w);
        float4 w = *(const float4*)&g_z[(size_t)(cb + row) * H2 + kq * 4];
        zc[kq * 4 + 0][row] = w.x; zc[kq * 4 + 1][row] = w.y;
        zc[kq * 4 + 2][row] = w.z; zc[kq * 4 + 3][row] = w.w;
    }
    __syncthreads();

    const int tc = tid & 15, tr = tid >> 4;
    const int r4 = tr * 4, c4 = tc * 4;

    ull acc[8][4] = {};   // [row i][j-pair]: pairs (c4+0,1) (c4+2,3) (c4+64,65) (c4+66,67)
    #pragma unroll
    for (int k = 0; k < H2; k++) {
        ulonglong2 a01 = *(ulonglong2*)&zr[k][r4];
        ulonglong2 a23 = *(ulonglong2*)&zr[k][r4 + 2];
        ulonglong2 a45 = *(ulonglong2*)&zr[k][r4 + 64];
        ulonglong2 a67 = *(ulonglong2*)&zr[k][r4 + 66];
        ulonglong2 b01 = *(ulonglong2*)&zc[k][c4];
        ulonglong2 b23 = *(ulonglong2*)&zc[k][c4 + 64];
        ull a[8] = {a01.x, a01.y, a23.x, a23.y, a45.x, a45.y, a67.x, a67.y};
        ull b[4] = {b01.x, b01.y, b23.x, b23.y};
        #pragma unroll
        for (int i = 0; i < 8; i++) {
            ffma2(acc[i][0], a[i], b[0]);
            ffma2(acc[i][1], a[i], b[1]);
            ffma2(acc[i][2], a[i], b[2]);
            ffma2(acc[i][3], a[i], b[3]);
        }
    }

    #pragma unroll
    for (int i = 0; i < 8; i++) {
        int row = rb + r4 + (i < 4 ? i : 60 + i);
        float2 p0 = unpk(acc[i][0]), p1 = unpk(acc[i][1]);
        float2 p2 = unpk(acc[i][2]), p3 = unpk(acc[i][3]);
        float4 o0, o1;
        o0.x = sigm(p0.x); o0.y = sigm(p0.y); o0.z = sigm(p1.x); o0.w = sigm(p1.y);
        o1.x = sigm(p2.x); o1.y = sigm(p2.y); o1.z = sigm(p3.x); o1.w = sigm(p3.y);
        *reinterpret_cast<float4*>(&out[(size_t)row * N_NODES + cb + c4])      = o0;
        *reinterpret_cast<float4*>(&out[(size_t)row * N_NODES + cb + c4 + 64]) = o1;
    }
}

// ---------------- launcher ----------------
extern "C" void kernel_launch(void* const* d_in, const int* in_sizes, int n_in,
                              void* d_out, int out_size) {
    const float* feat   = (const float*)d_in[0];
    const float* W0     = (const float*)d_in[1];
    const float* Wm     = (const float*)d_in[2];
    const float* gate_w = (const float*)d_in[3];
    const float* gate_b = (const float*)d_in[4];
    const float* t2w    = (const float*)d_in[5];
    const float* noise  = (const float*)d_in[6];
    const int*   src    = (const int*)d_in[7];
    const int*   dst    = (const int*)d_in[8];
    float* out = (float*)d_out;

    zero_kernel<<<(N_NODES * H1) / 256, 256>>>();
    deg_kernel<<<E_EDGES / 256, 256>>>(dst);
    norm_kernel<<<N_NODES / 256, 256>>>();
    gemm1_kernel<<<dim3(N_NODES / 128, 16), 256>>>(feat, W0);
    edge_h_kernel<<<(E_EDGES * 8) / 256, 256>>>(src, dst);
    relu_kernel<<<(N_NODES * H1) / 256, 256>>>();
    hw_kernel<<<(N_NODES * H2) / 256, 256>>>(Wm);
    edge2_kernel<<<(E_EDGES * 8) / 256, 256>>>(src, dst, gate_w, gate_b);
    nodez_kernel<<<(N_NODES * H2) / 256, 256>>>(t2w, noise);
    zzt_kernel<<<dim3(64, 64), 256>>>(out);
}

// round 8
// speedup vs baseline: 1.3138x; 1.0243x over previous
#include <cuda_runtime.h>

#define N_NODES 8192
#define F_DIM   2048
#define E_EDGES 262144
#define H1      32
#define H2      16
#define ALPHA   0.9f

typedef unsigned long long ull;

// ---------------- scratch (device globals; no allocs allowed) ----------------
__device__ float g_deg  [N_NODES];
__device__ float g_norm [N_NODES];
__device__ float g_WT   [H1 * F_DIM];     // W0 transposed: [n][k]
__device__ float g_xw   [N_NODES * H1];
__device__ float g_agg1 [N_NODES * H1];
__device__ float g_h    [N_NODES * H1];
__device__ float g_hw   [N_NODES * H2];
__device__ float g_agg2 [N_NODES * H2];
__device__ float g_zauto[N_NODES * H1];
__device__ float g_z    [N_NODES * H2];

// ---------------- f32x2 helpers ----------------
__device__ __forceinline__ ull dup2(float x) {
    ull r; asm("mov.b64 %0, {%1, %1};" : "=l"(r) : "f"(x)); return r;
}
__device__ __forceinline__ void ffma2(ull& d, ull a, ull b) {
    asm("fma.rn.f32x2 %0, %1, %2, %0;" : "+l"(d) : "l"(a), "l"(b));
}
__device__ __forceinline__ float2 unpk(ull v) {
    float2 r; asm("mov.b64 {%0, %1}, %2;" : "=f"(r.x), "=f"(r.y) : "l"(v)); return r;
}
__device__ __forceinline__ void red4(float* p, float a, float b, float c, float d) {
    asm volatile("red.global.add.v4.f32 [%0], {%1,%2,%3,%4};"
                 :: "l"(p), "f"(a), "f"(b), "f"(c), "f"(d) : "memory");
}
__device__ __forceinline__ void red1(float* p, float a) {
    asm volatile("red.global.add.f32 [%0], %1;" :: "l"(p), "f"(a) : "memory");
}
__device__ __forceinline__ float sigm(float x) {
    return __fdividef(1.0f, 1.0f + __expf(-x));
}

// ---------------- zero scratch ----------------
__global__ void zero_kernel() {
    int i = blockIdx.x * blockDim.x + threadIdx.x;
    if (i < N_NODES) g_deg[i] = 0.f;
    if (i < N_NODES * H1) { g_xw[i] = 0.f; g_agg1[i] = 0.f; g_zauto[i] = 0.f; }
    if (i < N_NODES * H2) g_agg2[i] = 0.f;
}

// ---------------- W0 transpose prep: WT[n][k] = W0[k][n] --------------------
__global__ void wt_kernel(const float* __restrict__ W0) {
    int i = blockIdx.x * blockDim.x + threadIdx.x;   // over 2048*32
    int k = i >> 5, n = i & 31;
    g_WT[n * F_DIM + k] = W0[i];
}

// ---------------- degree + norm ----------------
__global__ void deg_kernel(const int* __restrict__ dst) {
    int i = blockIdx.x * blockDim.x + threadIdx.x;
    if (i < E_EDGES) atomicAdd(&g_deg[dst[i]], 1.0f);
}

__global__ void norm_kernel() {
    int i = blockIdx.x * blockDim.x + threadIdx.x;
    if (i < N_NODES) g_norm[i] = rsqrtf(fmaxf(g_deg[i], 1.0f));
}

// ---------------- GEMM1: xw = feat @ W0 -------------------------------------
// BM=128, N=32, K-slice=128 (4 tiles of BK=32), SPLITK=16 -> grid (64,16).
// f32x2 pairs run over K (lo=even k, hi=odd k): both operands are natural
// contiguous pairs -> no duplication in smem, minimal L1 wavefronts.
// Thread tile 4 rows x 4 cols; cols = tx + {0,8,16,24} (conflict-free B LDS).
__global__ __launch_bounds__(256) void gemm1_kernel(const float* __restrict__ feat) {
    __shared__ float fs[128][36];    // [row][k] plain; stride 36 -> 16B-aligned rows
    __shared__ float wsT[32][132];   // [col][k] whole 128-k slice; stride 132

    const int tid = threadIdx.x;
    const int rowBase = blockIdx.x * 128;
    const int kBase   = blockIdx.y * 128;
    const int tx = tid & 7, ty = tid >> 3;
    const int r0 = ty * 4;

    const float* fb = feat + (size_t)rowBase * F_DIM + kBase;

    // ---- load whole B slice (32 cols x 128 k) once ----
    {
        int c = tid >> 3, j0 = tid & 7;
        const float* wrow = &g_WT[(size_t)c * F_DIM + kBase];
        #pragma unroll
        for (int i = 0; i < 4; i++) {
            int kk = (j0 + 8 * i) * 4;
            *(float4*)&wsT[c][kk] = *(const float4*)&wrow[kk];
        }
    }

    // feat tile load indices (4 float4 per thread per tile)
    int row_[4], kq_[4];
    #pragma unroll
    for (int i = 0; i < 4; i++) { int s = i * 256 + tid; row_[i] = s >> 3; kq_[i] = s & 7; }

    ull acc[4][4] = {};   // [row i][col j], pair = (even-k sum, odd-k sum)

    // prefetch tile 0
    float4 pf[4];
    #pragma unroll
    for (int i = 0; i < 4; i++)
        pf[i] = *(const float4*)&fb[(size_t)row_[i] * F_DIM + kq_[i] * 4];

    #pragma unroll
    for (int t = 0; t < 4; t++) {
        #pragma unroll
        for (int i = 0; i < 4; i++)
            *(float4*)&fs[row_[i]][kq_[i] * 4] = pf[i];
        __syncthreads();

        if (t < 3) {
            #pragma unroll
            for (int i = 0; i < 4; i++)
                pf[i] = *(const float4*)&fb[(size_t)row_[i] * F_DIM + (t + 1) * 32 + kq_[i] * 4];
        }

        const int kw = t * 32;
        #pragma unroll
        for (int k = 0; k < 32; k += 4) {
            ulonglong2 A[4], B[4];
            #pragma unroll
            for (int i = 0; i < 4; i++)
                A[i] = *(ulonglong2*)&fs[r0 + i][k];
            #pragma unroll
            for (int j = 0; j < 4; j++)
                B[j] = *(ulonglong2*)&wsT[tx + 8 * j][kw + k];
            #pragma unroll
            for (int i = 0; i < 4; i++)
                #pragma unroll
                for (int j = 0; j < 4; j++) {
                    ffma2(acc[i][j], A[i].x, B[j].x);
                    ffma2(acc[i][j], A[i].y, B[j].y);
                }
        }
        __syncthreads();
    }

    #pragma unroll
    for (int i = 0; i < 4; i++)
        #pragma unroll
        for (int j = 0; j < 4; j++) {
            float2 p = unpk(acc[i][j]);
            red1(&g_xw[(size_t)(rowBase + r0 + i) * H1 + tx + 8 * j], p.x + p.y);
        }
}

// ---------------- edge pass 1: agg1[dst] += norm[src] * xw[src] --------------
__global__ void edge_h_kernel(const int* __restrict__ src, const int* __restrict__ dst) {
    int t = blockIdx.x * blockDim.x + threadIdx.x;
    int e = t >> 3, q = t & 7;
    if (e >= E_EDGES) return;
    int s = __ldg(&src[e]);
    int d = __ldg(&dst[e]);
    float ns = g_norm[s];
    float4 v = *(const float4*)&g_xw[s * H1 + q * 4];
    red4(&g_agg1[d * H1 + q * 4], v.x * ns, v.y * ns, v.z * ns, v.w * ns);
}

// ---------------- h = relu(norm * agg1) ----------------
__global__ void relu_kernel() {
    int i = blockIdx.x * blockDim.x + threadIdx.x;
    if (i < N_NODES * H1) g_h[i] = fmaxf(g_norm[i >> 5] * g_agg1[i], 0.0f);
}

// ---------------- hw = norm * (h @ Wm) ----------------
__global__ void hw_kernel(const float* __restrict__ Wm) {
    int t = blockIdx.x * blockDim.x + threadIdx.x;
    if (t >= N_NODES * H2) return;
    int node = t >> 4, j = t & 15;
    float sum = 0.f;
    #pragma unroll
    for (int c = 0; c < H1; c++)
        sum += g_h[node * H1 + c] * __ldg(&Wm[c * H2 + j]);
    g_hw[t] = g_norm[node] * sum;
}

// ---------------- edge pass 2: gate + z_auto + agg2 (fused, 8 lanes/edge) ----
__global__ void edge2_kernel(const int* __restrict__ src, const int* __restrict__ dst,
                             const float* __restrict__ gate_w,
                             const float* __restrict__ gate_b) {
    int t = blockIdx.x * blockDim.x + threadIdx.x;
    int e = t >> 3, q = t & 7;
    if (e >= E_EDGES) return;
    int s = __ldg(&src[e]);
    int d = __ldg(&dst[e]);
    float4 hs = *(const float4*)&g_h[s * H1 + q * 4];
    float4 hd = *(const float4*)&g_h[d * H1 + q * 4];
    float4 w0 = __ldg((const float4*)&gate_w[q * 4]);
    float4 w1 = __ldg((const float4*)&gate_w[H1 + q * 4]);
    float gp = hd.x * w0.x + hd.y * w0.y + hd.z * w0.z + hd.w * w0.w
             + hs.x * w1.x + hs.y * w1.y + hs.z * w1.z + hs.w * w1.w;
    gp += __shfl_xor_sync(0xffffffffu, gp, 1);
    gp += __shfl_xor_sync(0xffffffffu, gp, 2);
    gp += __shfl_xor_sync(0xffffffffu, gp, 4);
    float g  = tanhf(gp + __ldg(&gate_b[0]));
    float ew = g * g_norm[d] * g_norm[s] * ALPHA;
    red4(&g_zauto[d * H1 + q * 4], hs.x * ew, hs.y * ew, hs.z * ew, hs.w * ew);
    if (q < 4) {
        float4 hw = *(const float4*)&g_hw[s * H2 + q * 4];
        red4(&g_agg2[d * H2 + q * 4], hw.x, hw.y, hw.z, hw.w);
    }
}

// ---------------- z = noise * exp((z_auto + a*h) @ t2w) + norm*agg2 ----------
__global__ void nodez_kernel(const float* __restrict__ t2w,
                             const float* __restrict__ noise) {
    int t = blockIdx.x * blockDim.x + threadIdx.x;
    if (t >= N_NODES * H2) return;
    int node = t >> 4, j = t & 15;
    float mean = g_norm[node] * g_agg2[t];
    float sum = 0.f;
    #pragma unroll
    for (int c = 0; c < H1; c++)
        sum += (g_zauto[node * H1 + c] + ALPHA * g_h[node * H1 + c]) * __ldg(&t2w[c * H2 + j]);
    g_z[t] = noise[t] * expf(sum) + mean;
}

// ---------------- out = sigmoid(z @ z^T), 128x128 tiles, 8x8/thread, f32x2 ---
__global__ __launch_bounds__(256) void zzt_kernel(float* __restrict__ out) {
    __shared__ ull   zr[H2][130];   // [k][row] duplicated {v,v} pairs
    __shared__ float zc[H2][132];   // [k][col]

    const int tid = threadIdx.x;
    const int rb = blockIdx.y * 128, cb = blockIdx.x * 128;

    #pragma unroll
    for (int i = 0; i < 2; i++) {
        int sIdx = tid + i * 256;
        int row = sIdx >> 2, kq = sIdx & 3;
        float4 v = *(const float4*)&g_z[(size_t)(rb + row) * H2 + kq * 4];
        zr[kq * 4 + 0][row] = dup2(v.x); zr[kq * 4 + 1][row] = dup2(v.y);
        zr[kq * 4 + 2][row] = dup2(v.z); zr[kq * 4 + 3][row] = dup2(v.w);
        float4 w = *(const float4*)&g_z[(size_t)(cb + row) * H2 + kq * 4];
        zc[kq * 4 + 0][row] = w.x; zc[kq * 4 + 1][row] = w.y;
        zc[kq * 4 + 2][row] = w.z; zc[kq * 4 + 3][row] = w.w;
    }
    __syncthreads();

    const int tc = tid & 15, tr = tid >> 4;
    const int r4 = tr * 4, c4 = tc * 4;

    ull acc[8][4] = {};
    #pragma unroll
    for (int k = 0; k < H2; k++) {
        ulonglong2 a01 = *(ulonglong2*)&zr[k][r4];
        ulonglong2 a23 = *(ulonglong2*)&zr[k][r4 + 2];
        ulonglong2 a45 = *(ulonglong2*)&zr[k][r4 + 64];
        ulonglong2 a67 = *(ulonglong2*)&zr[k][r4 + 66];
        ulonglong2 b01 = *(ulonglong2*)&zc[k][c4];
        ulonglong2 b23 = *(ulonglong2*)&zc[k][c4 + 64];
        ull a[8] = {a01.x, a01.y, a23.x, a23.y, a45.x, a45.y, a67.x, a67.y};
        ull b[4] = {b01.x, b01.y, b23.x, b23.y};
        #pragma unroll
        for (int i = 0; i < 8; i++) {
            ffma2(acc[i][0], a[i], b[0]);
            ffma2(acc[i][1], a[i], b[1]);
            ffma2(acc[i][2], a[i], b[2]);
            ffma2(acc[i][3], a[i], b[3]);
        }
    }

    #pragma unroll
    for (int i = 0; i < 8; i++) {
        int row = rb + r4 + (i < 4 ? i : 60 + i);
        float2 p0 = unpk(acc[i][0]), p1 = unpk(acc[i][1]);
        float2 p2 = unpk(acc[i][2]), p3 = unpk(acc[i][3]);
        float4 o0, o1;
        o0.x = sigm(p0.x); o0.y = sigm(p0.y); o0.z = sigm(p1.x); o0.w = sigm(p1.y);
        o1.x = sigm(p2.x); o1.y = sigm(p2.y); o1.z = sigm(p3.x); o1.w = sigm(p3.y);
        *reinterpret_cast<float4*>(&out[(size_t)row * N_NODES + cb + c4])      = o0;
        *reinterpret_cast<float4*>(&out[(size_t)row * N_NODES + cb + c4 + 64]) = o1;
    }
}

// ---------------- launcher ----------------
extern "C" void kernel_launch(void* const* d_in, const int* in_sizes, int n_in,
                              void* d_out, int out_size) {
    const float* feat   = (const float*)d_in[0];
    const float* W0     = (const float*)d_in[1];
    const float* Wm     = (const float*)d_in[2];
    const float* gate_w = (const float*)d_in[3];
    const float* gate_b = (const float*)d_in[4];
    const float* t2w    = (const float*)d_in[5];
    const float* noise  = (const float*)d_in[6];
    const int*   src    = (const int*)d_in[7];
    const int*   dst    = (const int*)d_in[8];
    float* out = (float*)d_out;

    zero_kernel<<<(N_NODES * H1) / 256, 256>>>();
    wt_kernel<<<(H1 * F_DIM) / 256, 256>>>(W0);
    deg_kernel<<<E_EDGES / 256, 256>>>(dst);
    norm_kernel<<<N_NODES / 256, 256>>>();
    gemm1_kernel<<<dim3(N_NODES / 128, 16), 256>>>(feat);
    edge_h_kernel<<<(E_EDGES * 8) / 256, 256>>>(src, dst);
    relu_kernel<<<(N_NODES * H1) / 256, 256>>>();
    hw_kernel<<<(N_NODES * H2) / 256, 256>>>(Wm);
    edge2_kernel<<<(E_EDGES * 8) / 256, 256>>>(src, dst, gate_w, gate_b);
    nodez_kernel<<<(N_NODES * H2) / 256, 256>>>(t2w, noise);
    zzt_kernel<<<dim3(64, 64), 256>>>(out);
}

// round 9
// speedup vs baseline: 1.3739x; 1.0457x over previous
#include <cuda_runtime.h>

#define N_NODES 8192
#define F_DIM   2048
#define E_EDGES 262144
#define H1      32
#define H2      16
#define ALPHA   0.9f

typedef unsigned long long ull;

// ---------------- scratch (device globals; no allocs allowed) ----------------
__device__ float g_deg  [N_NODES];
__device__ float g_norm [N_NODES];
__device__ float g_WT   [H1 * F_DIM];     // W0 transposed: [n][k]
__device__ float g_xw   [N_NODES * H1];
__device__ float g_agg1 [N_NODES * H1];
__device__ float g_h    [N_NODES * H1];
__device__ float g_hw   [N_NODES * H2];
__device__ float g_agg2 [N_NODES * H2];
__device__ float g_zauto[N_NODES * H1];
__device__ float g_z    [N_NODES * H2];

// ---------------- f32x2 helpers ----------------
__device__ __forceinline__ ull dup2(float x) {
    ull r; asm("mov.b64 %0, {%1, %1};" : "=l"(r) : "f"(x)); return r;
}
__device__ __forceinline__ void ffma2(ull& d, ull a, ull b) {
    asm("fma.rn.f32x2 %0, %1, %2, %0;" : "+l"(d) : "l"(a), "l"(b));
}
__device__ __forceinline__ float2 unpk(ull v) {
    float2 r; asm("mov.b64 {%0, %1}, %2;" : "=f"(r.x), "=f"(r.y) : "l"(v)); return r;
}
__device__ __forceinline__ void red4(float* p, float a, float b, float c, float d) {
    asm volatile("red.global.add.v4.f32 [%0], {%1,%2,%3,%4};"
                 :: "l"(p), "f"(a), "f"(b), "f"(c), "f"(d) : "memory");
}
// sigmoid via single-MUFU hardware tanh: sigm(x) = 0.5*tanh(x/2) + 0.5
__device__ __forceinline__ float sigm(float x) {
    float t;
    asm("tanh.approx.f32 %0, %1;" : "=f"(t) : "f"(0.5f * x));
    return fmaf(0.5f, t, 0.5f);
}

// ---------------- init: zero scratch + build WT (fused) ----------------
__global__ void init_kernel(const float* __restrict__ W0) {
    int i = blockIdx.x * blockDim.x + threadIdx.x;   // grid covers N_NODES*H1
    if (i < N_NODES) g_deg[i] = 0.f;
    if (i < N_NODES * H1) { g_xw[i] = 0.f; g_agg1[i] = 0.f; g_zauto[i] = 0.f; }
    if (i < N_NODES * H2) g_agg2[i] = 0.f;
    if (i < H1 * F_DIM) {
        int k = i >> 5, n = i & 31;
        g_WT[n * F_DIM + k] = W0[i];
    }
}

// ---------------- degree + norm ----------------
__global__ void deg_kernel(const int* __restrict__ dst) {
    int i = blockIdx.x * blockDim.x + threadIdx.x;
    if (i < E_EDGES) atomicAdd(&g_deg[dst[i]], 1.0f);
}

__global__ void norm_kernel() {
    int i = blockIdx.x * blockDim.x + threadIdx.x;
    if (i < N_NODES) g_norm[i] = rsqrtf(fmaxf(g_deg[i], 1.0f));
}

// ---------------- GEMM1: xw = feat @ W0 -------------------------------------
// BM=128, N=32, K-slice=128 (4 tiles of BK=32), SPLITK=16 -> grid (64,16).
// f32x2 pairs run over K (lo=even k, hi=odd k). Epilogue stages the partial
// 128x32 tile in smem (reusing fs) so global reduction is 4x red.v4/thread
// instead of 16x scalar red (REDG issue cost ~4x lower).
__global__ __launch_bounds__(256) void gemm1_kernel(const float* __restrict__ feat) {
    __shared__ float fs[128][36];    // [row][k] plain; stride 36 -> 16B-aligned rows
    __shared__ float wsT[32][132];   // [col][k] whole 128-k slice; stride 132

    const int tid = threadIdx.x;
    const int rowBase = blockIdx.x * 128;
    const int kBase   = blockIdx.y * 128;
    const int tx = tid & 7, ty = tid >> 3;
    const int r0 = ty * 4;

    const float* fb = feat + (size_t)rowBase * F_DIM + kBase;

    // ---- load whole B slice (32 cols x 128 k) once ----
    {
        int c = tid >> 3, j0 = tid & 7;
        const float* wrow = &g_WT[(size_t)c * F_DIM + kBase];
        #pragma unroll
        for (int i = 0; i < 4; i++) {
            int kk = (j0 + 8 * i) * 4;
            *(float4*)&wsT[c][kk] = *(const float4*)&wrow[kk];
        }
    }

    // feat tile load indices (4 float4 per thread per tile)
    int row_[4], kq_[4];
    #pragma unroll
    for (int i = 0; i < 4; i++) { int s = i * 256 + tid; row_[i] = s >> 3; kq_[i] = s & 7; }

    ull acc[4][4] = {};   // [row i][col j], pair = (even-k sum, odd-k sum)

    // prefetch tile 0
    float4 pf[4];
    #pragma unroll
    for (int i = 0; i < 4; i++)
        pf[i] = *(const float4*)&fb[(size_t)row_[i] * F_DIM + kq_[i] * 4];

    #pragma unroll
    for (int t = 0; t < 4; t++) {
        #pragma unroll
        for (int i = 0; i < 4; i++)
            *(float4*)&fs[row_[i]][kq_[i] * 4] = pf[i];
        __syncthreads();

        if (t < 3) {
            #pragma unroll
            for (int i = 0; i < 4; i++)
                pf[i] = *(const float4*)&fb[(size_t)row_[i] * F_DIM + (t + 1) * 32 + kq_[i] * 4];
        }

        const int kw = t * 32;
        #pragma unroll
        for (int k = 0; k < 32; k += 4) {
            ulonglong2 A[4], B[4];
            #pragma unroll
            for (int i = 0; i < 4; i++)
                A[i] = *(ulonglong2*)&fs[r0 + i][k];
            #pragma unroll
            for (int j = 0; j < 4; j++)
                B[j] = *(ulonglong2*)&wsT[tx + 8 * j][kw + k];
            #pragma unroll
            for (int i = 0; i < 4; i++)
                #pragma unroll
                for (int j = 0; j < 4; j++) {
                    ffma2(acc[i][j], A[i].x, B[j].x);
                    ffma2(acc[i][j], A[i].y, B[j].y);
                }
        }
        __syncthreads();
    }

    // ---- epilogue: stage partial tile in fs, then contiguous red.v4 ----
    #pragma unroll
    for (int i = 0; i < 4; i++)
        #pragma unroll
        for (int j = 0; j < 4; j++) {
            float2 p = unpk(acc[i][j]);
            fs[r0 + i][tx + 8 * j] = p.x + p.y;
        }
    __syncthreads();

    // thread -> half-row: row = tid>>1, cols (tid&1)*16 .. +15  (4 x red.v4)
    {
        int row = tid >> 1, cs = (tid & 1) * 16;
        float* gp = &g_xw[(size_t)(rowBase + row) * H1 + cs];
        #pragma unroll
        for (int q = 0; q < 4; q++) {
            float4 v = *(float4*)&fs[row][cs + q * 4];
            red4(gp + q * 4, v.x, v.y, v.z, v.w);
        }
    }
}

// ---------------- edge pass 1: agg1[dst] += norm[src] * xw[src] --------------
__global__ void edge_h_kernel(const int* __restrict__ src, const int* __restrict__ dst) {
    int t = blockIdx.x * blockDim.x + threadIdx.x;
    int e = t >> 3, q = t & 7;
    if (e >= E_EDGES) return;
    int s = __ldg(&src[e]);
    int d = __ldg(&dst[e]);
    float ns = g_norm[s];
    float4 v = *(const float4*)&g_xw[s * H1 + q * 4];
    red4(&g_agg1[d * H1 + q * 4], v.x * ns, v.y * ns, v.z * ns, v.w * ns);
}

// ---------------- fused: h = relu(norm*agg1); hw = norm*(h @ Wm) -------------
// 8 nodes per 256-thread block: phase 1 one lane per (node, h-col),
// phase 2 first 128 threads compute (node, hw-col) from smem h.
__global__ __launch_bounds__(256) void relu_hw_kernel(const float* __restrict__ Wm) {
    __shared__ float sh[8][33];
    int tid = threadIdx.x;
    int local = tid >> 5, lane = tid & 31;
    int node = blockIdx.x * 8 + local;
    float h = fmaxf(g_norm[node] * g_agg1[node * H1 + lane], 0.0f);
    g_h[node * H1 + lane] = h;
    sh[local][lane] = h;
    __syncthreads();
    if (tid < 128) {
        int ln = tid >> 4, j = tid & 15;
        int nd = blockIdx.x * 8 + ln;
        float sum = 0.f;
        #pragma unroll
        for (int c = 0; c < H1; c++)
            sum += sh[ln][c] * __ldg(&Wm[c * H2 + j]);
        g_hw[nd * H2 + j] = g_norm[nd] * sum;
    }
}

// ---------------- edge pass 2: gate + z_auto + agg2 (fused, 8 lanes/edge) ----
__global__ void edge2_kernel(const int* __restrict__ src, const int* __restrict__ dst,
                             const float* __restrict__ gate_w,
                             const float* __restrict__ gate_b) {
    int t = blockIdx.x * blockDim.x + threadIdx.x;
    int e = t >> 3, q = t & 7;
    if (e >= E_EDGES) return;
    int s = __ldg(&src[e]);
    int d = __ldg(&dst[e]);
    float4 hs = *(const float4*)&g_h[s * H1 + q * 4];
    float4 hd = *(const float4*)&g_h[d * H1 + q * 4];
    float4 w0 = __ldg((const float4*)&gate_w[q * 4]);
    float4 w1 = __ldg((const float4*)&gate_w[H1 + q * 4]);
    float gp = hd.x * w0.x + hd.y * w0.y + hd.z * w0.z + hd.w * w0.w
             + hs.x * w1.x + hs.y * w1.y + hs.z * w1.z + hs.w * w1.w;
    gp += __shfl_xor_sync(0xffffffffu, gp, 1);
    gp += __shfl_xor_sync(0xffffffffu, gp, 2);
    gp += __shfl_xor_sync(0xffffffffu, gp, 4);
    float g  = tanhf(gp + __ldg(&gate_b[0]));
    float ew = g * g_norm[d] * g_norm[s] * ALPHA;
    red4(&g_zauto[d * H1 + q * 4], hs.x * ew, hs.y * ew, hs.z * ew, hs.w * ew);
    if (q < 4) {
        float4 hw = *(const float4*)&g_hw[s * H2 + q * 4];
        red4(&g_agg2[d * H2 + q * 4], hw.x, hw.y, hw.z, hw.w);
    }
}

// ---------------- z = noise * exp((z_auto + a*h) @ t2w) + norm*agg2 ----------
__global__ void nodez_kernel(const float* __restrict__ t2w,
                             const float* __restrict__ noise) {
    int t = blockIdx.x * blockDim.x + threadIdx.x;
    if (t >= N_NODES * H2) return;
    int node = t >> 4, j = t & 15;
    float mean = g_norm[node] * g_agg2[t];
    float sum = 0.f;
    #pragma unroll
    for (int c = 0; c < H1; c++)
        sum += (g_zauto[node * H1 + c] + ALPHA * g_h[node * H1 + c]) * __ldg(&t2w[c * H2 + j]);
    g_z[t] = noise[t] * expf(sum) + mean;
}

// ---------------- out = sigmoid(z @ z^T), 128x128 tiles, 8x8/thread, f32x2 ---
__global__ __launch_bounds__(256) void zzt_kernel(float* __restrict__ out) {
    __shared__ ull   zr[H2][130];   // [k][row] duplicated {v,v} pairs
    __shared__ float zc[H2][132];   // [k][col]

    const int tid = threadIdx.x;
    const int rb = blockIdx.y * 128, cb = blockIdx.x * 128;

    #pragma unroll
    for (int i = 0; i < 2; i++) {
        int sIdx = tid + i * 256;
        int row = sIdx >> 2, kq = sIdx & 3;
        float4 v = *(const float4*)&g_z[(size_t)(rb + row) * H2 + kq * 4];
        zr[kq * 4 + 0][row] = dup2(v.x); zr[kq * 4 + 1][row] = dup2(v.y);
        zr[kq * 4 + 2][row] = dup2(v.z); zr[kq * 4 + 3][row] = dup2(v.w);
        float4 w = *(const float4*)&g_z[(size_t)(cb + row) * H2 + kq * 4];
        zc[kq * 4 + 0][row] = w.x; zc[kq * 4 + 1][row] = w.y;
        zc[kq * 4 + 2][row] = w.z; zc[kq * 4 + 3][row] = w.w;
    }
    __syncthreads();

    const int tc = tid & 15, tr = tid >> 4;
    const int r4 = tr * 4, c4 = tc * 4;

    ull acc[8][4] = {};
    #pragma unroll
    for (int k = 0; k < H2; k++) {
        ulonglong2 a01 = *(ulonglong2*)&zr[k][r4];
        ulonglong2 a23 = *(ulonglong2*)&zr[k][r4 + 2];
        ulonglong2 a45 = *(ulonglong2*)&zr[k][r4 + 64];
        ulonglong2 a67 = *(ulonglong2*)&zr[k][r4 + 66];
        ulonglong2 b01 = *(ulonglong2*)&zc[k][c4];
        ulonglong2 b23 = *(ulonglong2*)&zc[k][c4 + 64];
        ull a[8] = {a01.x, a01.y, a23.x, a23.y, a45.x, a45.y, a67.x, a67.y};
        ull b[4] = {b01.x, b01.y, b23.x, b23.y};
        #pragma unroll
        for (int i = 0; i < 8; i++) {
            ffma2(acc[i][0], a[i], b[0]);
            ffma2(acc[i][1], a[i], b[1]);
            ffma2(acc[i][2], a[i], b[2]);
            ffma2(acc[i][3], a[i], b[3]);
        }
    }

    #pragma unroll
    for (int i = 0; i < 8; i++) {
        int row = rb + r4 + (i < 4 ? i : 60 + i);
        float2 p0 = unpk(acc[i][0]), p1 = unpk(acc[i][1]);
        float2 p2 = unpk(acc[i][2]), p3 = unpk(acc[i][3]);
        float4 o0, o1;
        o0.x = sigm(p0.x); o0.y = sigm(p0.y); o0.z = sigm(p1.x); o0.w = sigm(p1.y);
        o1.x = sigm(p2.x); o1.y = sigm(p2.y); o1.z = sigm(p3.x); o1.w = sigm(p3.y);
        *reinterpret_cast<float4*>(&out[(size_t)row * N_NODES + cb + c4])      = o0;
        *reinterpret_cast<float4*>(&out[(size_t)row * N_NODES + cb + c4 + 64]) = o1;
    }
}

// ---------------- launcher ----------------
extern "C" void kernel_launch(void* const* d_in, const int* in_sizes, int n_in,
                              void* d_out, int out_size) {
    const float* feat   = (const float*)d_in[0];
    const float* W0     = (const float*)d_in[1];
    const float* Wm     = (const float*)d_in[2];
    const float* gate_w = (const float*)d_in[3];
    const float* gate_b = (const float*)d_in[4];
    const float* t2w    = (const float*)d_in[5];
    const float* noise  = (const float*)d_in[6];
    const int*   src    = (const int*)d_in[7];
    const int*   dst    = (const int*)d_in[8];
    float* out = (float*)d_out;

    init_kernel<<<(N_NODES * H1) / 256, 256>>>(W0);
    deg_kernel<<<E_EDGES / 256, 256>>>(dst);
    norm_kernel<<<N_NODES / 256, 256>>>();
    gemm1_kernel<<<dim3(N_NODES / 128, 16), 256>>>(feat);
    edge_h_kernel<<<(E_EDGES * 8) / 256, 256>>>(src, dst);
    relu_hw_kernel<<<N_NODES / 8, 256>>>(Wm);
    edge2_kernel<<<(E_EDGES * 8) / 256, 256>>>(src, dst, gate_w, gate_b);
    nodez_kernel<<<(N_NODES * H2) / 256, 256>>>(t2w, noise);
    zzt_kernel<<<dim3(64, 64), 256>>>(out);
}